// round 2
// baseline (speedup 1.0000x reference)
#include <cuda_runtime.h>
#include <math.h>

#define NG    2048
#define NPG   24
#define EPG   288
#define KGB   32
#define EMB   32
#define DH    64
#define NT    256
#define NPAIR (NPG*NPG)          // 576
#define NATOM 10

// shared memory layout (in 4-byte words)
#define OFF_P     0
#define OFF_X     (OFF_P     + NPAIR*KGB)     // 18432
#define OFF_S     (OFF_X     + NPAIR)         // +576
#define OFF_GNF   (OFF_S     + NPG*KGB)       // +768
#define OFF_WEP   (OFF_GNF   + NPG*EMB)       // +768
#define OFF_MUL   (OFF_WEP   + KGB*EMB)       // +1024
#define OFF_BIAS  (OFF_MUL   + NATOM*NATOM)   // +100
#define OFF_MEAN  (OFF_BIAS  + NATOM*NATOM)   // +100
#define OFF_ISTD  (OFF_MEAN  + KGB)
#define OFF_NORM  (OFF_ISTD  + KGB)
#define OFF_BEP   (OFF_NORM  + KGB)
#define OFF_BN    (OFF_BEP   + EMB)
#define OFF_BE    (OFF_BN    + DH)
#define OFF_AE    (OFF_BE    + DH)            // atom_emb 10*32
#define OFF_POS   (OFF_AE    + NATOM*EMB)     // 72
#define OFF_PAIR  (OFF_POS   + NPG*3)         // 288 ints (edge pair offsets)
#define OFF_Z     (OFF_PAIR  + EPG)           // 24 ints
#define SMEM_WORDS (OFF_Z + NPG)
#define SMEM_BYTES (SMEM_WORDS * 4)

extern __shared__ float sm[];

__global__ __launch_bounds__(NT, 2)
void gps_graph_kernel(const int* __restrict__ z,
                      const float* __restrict__ pos,
                      const int* __restrict__ edge_index,
                      const float* __restrict__ atom_emb,
                      const float* __restrict__ Wep,
                      const float* __restrict__ bep,
                      const float* __restrict__ means,
                      const float* __restrict__ stds,
                      const float* __restrict__ gmul,
                      const float* __restrict__ gbias,
                      const float* __restrict__ Wn,
                      const float* __restrict__ bn,
                      const float* __restrict__ We,
                      const float* __restrict__ be,
                      float* __restrict__ out_nodes,
                      float* __restrict__ out_edges,
                      int E)
{
    const int g   = blockIdx.x;
    const int tid = threadIdx.x;
    const int zbase = g * NPG;

    float* P     = sm + OFF_P;
    float* Xv    = sm + OFF_X;
    float* Ssum  = sm + OFF_S;
    float* Gnf   = sm + OFF_GNF;
    float* sWep  = sm + OFF_WEP;
    float* sMul  = sm + OFF_MUL;
    float* sBias = sm + OFF_BIAS;
    float* sMean = sm + OFF_MEAN;
    float* sIstd = sm + OFF_ISTD;
    float* sNorm = sm + OFF_NORM;
    float* sBep  = sm + OFF_BEP;
    float* sBn   = sm + OFF_BN;
    float* sBe   = sm + OFF_BE;
    float* sAe   = sm + OFF_AE;
    float* sPos  = sm + OFF_POS;
    int*   sPair = (int*)(sm + OFF_PAIR);
    int*   sZ    = (int*)(sm + OFF_Z);

    // ---- cooperative loads ----
    if (tid < NPG) sZ[tid] = z[zbase + tid];
    for (int t = tid; t < NPG*3; t += NT) sPos[t] = pos[zbase*3 + t];
    for (int t = tid; t < KGB*EMB; t += NT) sWep[t] = Wep[t];
    for (int t = tid; t < NATOM*NATOM; t += NT) { sMul[t] = gmul[t]; sBias[t] = gbias[t]; }
    if (tid < KGB) {
        float s = fabsf(stds[tid]) + 1e-5f;
        sMean[tid] = means[tid];
        sIstd[tid] = 1.0f / s;
        sNorm[tid] = 0.3989422804014327f / s;   // 1/(sqrt(2*pi)*s)
    }
    if (tid >= KGB && tid < 2*KGB) sBep[tid - KGB] = bep[tid - KGB];
    if (tid >= 64 && tid < 128)  sBn[tid - 64] = bn[tid - 64];
    if (tid >= 128 && tid < 192) sBe[tid - 128] = be[tid - 128];
    for (int t = tid; t < NATOM*EMB; t += NT) sAe[t] = atom_emb[t];
    __syncthreads();

    // ---- Stage A: per-pair affine argument x = mul[et]*dist + bias[et] ----
    for (int p = tid; p < NPAIR; p += NT) {
        int i = p / NPG;
        int j = p - i * NPG;
        float dx = sPos[i*3+0] - sPos[j*3+0];
        float dy = sPos[i*3+1] - sPos[j*3+1];
        float dz = sPos[i*3+2] - sPos[j*3+2];
        float sq = dx*dx + dy*dy + dz*dz;
        float dist = (sq == 0.0f) ? 0.0f : sqrtf(sq);
        int et = sZ[i] * NATOM + sZ[j];
        Xv[p] = sMul[et] * dist + sBias[et];
    }
    __syncthreads();

    // ---- Stage B: Gaussian basis P[pair][k] ----
    {
        const int k = tid & (KGB - 1);
        const float mk = sMean[k], ik = sIstd[k], nk = sNorm[k];
        for (int p = (tid >> 5); p < NPAIR; p += (NT / KGB)) {   // 8 pairs in flight
            float a = (Xv[p] - mk) * ik;
            P[p * KGB + k] = nk * __expf(-0.5f * a * a);
        }
    }
    __syncthreads();

    // ---- Stage C: node sums  S[i][k] = sum_j P[i*24+j][k] ----
    for (int t = tid; t < NPG * KGB; t += NT) {
        int i = t >> 5, k = t & 31;
        const float* row = P + (i * NPG) * KGB + k;
        float s = 0.0f;
        #pragma unroll
        for (int j = 0; j < NPG; ++j) s += row[j * KGB];
        Ssum[t] = s;
    }
    // ---- edge pair offsets (independent, covered by the next sync) ----
    {
        const int ebase = g * EPG;
        for (int e = tid; e < EPG; e += NT) {
            int src = edge_index[ebase + e];
            int dst = edge_index[E + ebase + e];
            sPair[e] = ((dst - zbase) * NPG + (src - zbase)) * KGB;
        }
    }
    __syncthreads();

    // ---- Stage D: gnf = atom_emb[z_i] + S @ Wep + bep ----
    for (int t = tid; t < NPG * EMB; t += NT) {
        int i = t >> 5, m = t & 31;
        float acc = sAe[sZ[i] * EMB + m] + sBep[m];
        #pragma unroll
        for (int k = 0; k < KGB; ++k) acc += Ssum[i * KGB + k] * sWep[k * EMB + m];
        Gnf[t] = acc;
    }
    __syncthreads();

    // ---- Stage E: node_feat = gnf @ W_nodes + b_nodes ----
    {
        const int d = tid & (DH - 1);
        const int isub = tid >> 6;   // 0..3
        float wn[EMB];
        #pragma unroll
        for (int m = 0; m < EMB; ++m) wn[m] = Wn[m * DH + d];
        for (int i = isub; i < NPG; i += NT / DH) {
            float acc = sBn[d];
            #pragma unroll
            for (int m = 0; m < EMB; ++m) acc += Gnf[i * EMB + m] * wn[m];
            out_nodes[(size_t)(zbase + i) * DH + d] = acc;
        }
    }

    // ---- Stage F: edge_feat = P[dst_l][src_l] @ W_edges + b_edges ----
    {
        const int d = tid & (DH - 1);
        const int esub = tid >> 6;   // 0..3
        float we[KGB];
        #pragma unroll
        for (int k = 0; k < KGB; ++k) we[k] = We[k * DH + d];
        const int ebase = g * EPG;
        const float beD = sBe[d];
        #pragma unroll 2
        for (int e = esub; e < EPG; e += NT / DH) {
            const float4* pv = (const float4*)(P + sPair[e]);
            float acc = beD;
            #pragma unroll
            for (int q = 0; q < KGB / 4; ++q) {
                float4 v = pv[q];
                acc += v.x * we[q*4+0];
                acc += v.y * we[q*4+1];
                acc += v.z * we[q*4+2];
                acc += v.w * we[q*4+3];
            }
            out_edges[(size_t)(ebase + e) * DH + d] = acc;
        }
    }
}

extern "C" void kernel_launch(void* const* d_in, const int* in_sizes, int n_in,
                              void* d_out, int out_size)
{
    const int*   z    = (const int*)  d_in[0];
    const float* pos  = (const float*)d_in[1];
    // d_in[2] = batch_mapping (implied by layout; unused)
    const int*   ei   = (const int*)  d_in[3];
    const float* ae   = (const float*)d_in[4];
    const float* Wep  = (const float*)d_in[5];
    const float* bep  = (const float*)d_in[6];
    const float* mea  = (const float*)d_in[7];
    const float* stds = (const float*)d_in[8];
    const float* gmul = (const float*)d_in[9];
    const float* gbia = (const float*)d_in[10];
    const float* Wn   = (const float*)d_in[11];
    const float* bn   = (const float*)d_in[12];
    const float* We   = (const float*)d_in[13];
    const float* be   = (const float*)d_in[14];

    const int N = in_sizes[0];          // 49152
    const int E = in_sizes[3] / 2;      // 589824
    const int g = N / NPG;              // 2048

    float* out_nodes = (float*)d_out;
    float* out_edges = out_nodes + (size_t)N * DH;

    cudaFuncSetAttribute(gps_graph_kernel,
                         cudaFuncAttributeMaxDynamicSharedMemorySize, SMEM_BYTES);

    gps_graph_kernel<<<g, NT, SMEM_BYTES>>>(
        z, pos, ei, ae, Wep, bep, mea, stds, gmul, gbia,
        Wn, bn, We, be, out_nodes, out_edges, E);
}

// round 3
// speedup vs baseline: 1.2468x; 1.2468x over previous
#include <cuda_runtime.h>
#include <math.h>

#define NG    2048
#define NPG   24
#define EPG   288
#define KGB   32
#define EMB   32
#define DH    64
#define NT    256
#define NPAIR (NPG*NPG)          // 576
#define NATOM 10

typedef unsigned long long ull;

// packed fp32x2 helpers (Blackwell f32x2 pipe — PTX-only, ptxas won't auto-fuse)
__device__ __forceinline__ ull pk2(float lo, float hi) {
    ull r; asm("mov.b64 %0, {%1, %2};" : "=l"(r) : "f"(lo), "f"(hi)); return r;
}
__device__ __forceinline__ void upk2(ull v, float& lo, float& hi) {
    asm("mov.b64 {%0, %1}, %2;" : "=f"(lo), "=f"(hi) : "l"(v));
}
__device__ __forceinline__ ull ffma2(ull a, ull b, ull c) {
    ull d; asm("fma.rn.f32x2 %0, %1, %2, %3;" : "=l"(d) : "l"(a), "l"(b), "l"(c)); return d;
}
__device__ __forceinline__ ull fmul2(ull a, ull b) {
    ull d; asm("mul.rn.f32x2 %0, %1, %2;" : "=l"(d) : "l"(a), "l"(b)); return d;
}
__device__ __forceinline__ ull fadd2(ull a, ull b) {
    ull d; asm("add.rn.f32x2 %0, %1, %2;" : "=l"(d) : "l"(a), "l"(b)); return d;
}

// shared memory layout (4-byte words)
#define OFF_P     0
#define OFF_X     (OFF_P     + NPAIR*KGB)     // 18432
#define OFF_S     (OFF_X     + NPAIR)         // 19008
#define OFF_GNF   (OFF_S     + NPG*KGB)       // 19776
#define OFF_WEP   (OFF_GNF   + NPG*EMB)       // 20544 (packed ull [kk][m], 512 ull)
#define OFF_MUL   (OFF_WEP   + KGB*EMB)       // 21568
#define OFF_BIAS  (OFF_MUL   + NATOM*NATOM)
#define OFF_MEAN  (OFF_BIAS  + NATOM*NATOM)
#define OFF_ISTD  (OFF_MEAN  + KGB)
#define OFF_NORM  (OFF_ISTD  + KGB)
#define OFF_BEP   (OFF_NORM  + KGB)
#define OFF_BN    (OFF_BEP   + EMB)
#define OFF_BE    (OFF_BN    + DH)
#define OFF_AE    (OFF_BE    + DH)
#define OFF_POS   (OFF_AE    + NATOM*EMB)
#define OFF_PAIR  (OFF_POS   + NPG*3)
#define OFF_Z     (OFF_PAIR  + EPG)
#define SMEM_WORDS (OFF_Z + NPG)
#define SMEM_BYTES (SMEM_WORDS * 4)

extern __shared__ float sm[];

__global__ __launch_bounds__(NT, 2)
void gps_graph_kernel(const int* __restrict__ z,
                      const float* __restrict__ pos,
                      const int* __restrict__ edge_index,
                      const float* __restrict__ atom_emb,
                      const float* __restrict__ Wep,
                      const float* __restrict__ bep,
                      const float* __restrict__ means,
                      const float* __restrict__ stds,
                      const float* __restrict__ gmul,
                      const float* __restrict__ gbias,
                      const float* __restrict__ Wn,
                      const float* __restrict__ bn,
                      const float* __restrict__ We,
                      const float* __restrict__ be,
                      float* __restrict__ out_nodes,
                      float* __restrict__ out_edges,
                      int E)
{
    const int g   = blockIdx.x;
    const int tid = threadIdx.x;
    const int zbase = g * NPG;

    float* P     = sm + OFF_P;
    float* Xv    = sm + OFF_X;
    float* Ssum  = sm + OFF_S;
    float* Gnf   = sm + OFF_GNF;
    ull*   sWep2 = (ull*)(sm + OFF_WEP);     // [kk][m] packed over k-pairs
    float* sMul  = sm + OFF_MUL;
    float* sBias = sm + OFF_BIAS;
    float* sMean = sm + OFF_MEAN;
    float* sIstd = sm + OFF_ISTD;
    float* sNorm = sm + OFF_NORM;
    float* sBep  = sm + OFF_BEP;
    float* sBn   = sm + OFF_BN;
    float* sBe   = sm + OFF_BE;
    float* sAe   = sm + OFF_AE;
    float* sPos  = sm + OFF_POS;
    int*   sPair = (int*)(sm + OFF_PAIR);
    int*   sZ    = (int*)(sm + OFF_Z);

    // ---- cooperative loads ----
    if (tid < NPG) sZ[tid] = z[zbase + tid];
    for (int t = tid; t < NPG*3; t += NT) sPos[t] = pos[zbase*3 + t];
    // Wep packed over k-pairs, layout [kk][m] so LDS by lane-m is conflict-free
    for (int t = tid; t < (KGB/2)*EMB; t += NT) {
        int kk = t >> 5, m = t & 31;
        sWep2[kk * EMB + m] = pk2(Wep[(2*kk)*EMB + m], Wep[(2*kk+1)*EMB + m]);
    }
    for (int t = tid; t < NATOM*NATOM; t += NT) { sMul[t] = gmul[t]; sBias[t] = gbias[t]; }
    if (tid < KGB) {
        float s = fabsf(stds[tid]) + 1e-5f;
        sMean[tid] = means[tid];
        sIstd[tid] = 1.0f / s;
        sNorm[tid] = 0.3989422804014327f / s;
    }
    if (tid >= KGB && tid < 2*KGB) sBep[tid - KGB] = bep[tid - KGB];
    if (tid >= 64 && tid < 128)  sBn[tid - 64] = bn[tid - 64];
    if (tid >= 128 && tid < 192) sBe[tid - 128] = be[tid - 128];
    for (int t = tid; t < NATOM*EMB; t += NT) sAe[t] = atom_emb[t];
    __syncthreads();

    // ---- Stage A: per-pair affine argument x = mul[et]*dist + bias[et] ----
    for (int p = tid; p < NPAIR; p += NT) {
        int i = p / NPG;
        int j = p - i * NPG;
        float dx = sPos[i*3+0] - sPos[j*3+0];
        float dy = sPos[i*3+1] - sPos[j*3+1];
        float dz = sPos[i*3+2] - sPos[j*3+2];
        float sq = dx*dx + dy*dy + dz*dz;
        float dist = (sq == 0.0f) ? 0.0f : sqrtf(sq);
        int et = sZ[i] * NATOM + sZ[j];
        Xv[p] = sMul[et] * dist + sBias[et];
    }
    __syncthreads();

    // ---- Stage B: Gaussian basis P[pair][k], packed over k-pairs ----
    {
        const int kk = tid & 15;                       // k-pair 0..15
        const float i0 = sIstd[2*kk], i1 = sIstd[2*kk+1];
        const ull i2  = pk2(i0, i1);
        const ull mi2 = pk2(-sMean[2*kk]*i0, -sMean[2*kk+1]*i1);
        const ull n2  = pk2(sNorm[2*kk], sNorm[2*kk+1]);
        const ull h2  = pk2(-0.5f, -0.5f);
        ull* P2 = (ull*)P;
        for (int p = (tid >> 4); p < NPAIR; p += (NT/16)) {
            float x = Xv[p];
            ull x2 = pk2(x, x);
            ull a  = ffma2(x2, i2, mi2);               // (x - m)/s
            ull arg = fmul2(fmul2(a, a), h2);          // -0.5 a^2
            float alo, ahi; upk2(arg, alo, ahi);
            ull ex = pk2(__expf(alo), __expf(ahi));
            P2[p * (KGB/2) + kk] = fmul2(ex, n2);
        }
    }
    __syncthreads();

    // ---- Stage C: node sums  S[i][2kk..2kk+1] = sum_j P[i*24+j][...] ----
    {
        const ull* P2 = (const ull*)P;
        ull* S2 = (ull*)Ssum;
        for (int t = tid; t < NPG * (KGB/2); t += NT) {
            int i = t >> 4, kk = t & 15;
            const ull* row = P2 + (i * NPG) * (KGB/2) + kk;
            ull s = 0;
            #pragma unroll
            for (int j = 0; j < NPG; ++j) s = fadd2(s, row[j * (KGB/2)]);
            S2[t] = s;
        }
    }
    // ---- edge pair offsets (independent, covered by the next sync) ----
    {
        const int ebase = g * EPG;
        for (int e = tid; e < EPG; e += NT) {
            int src = edge_index[ebase + e];
            int dst = edge_index[E + ebase + e];
            sPair[e] = ((dst - zbase) * NPG + (src - zbase)) * KGB;
        }
    }
    __syncthreads();

    // ---- Stage D: gnf = atom_emb[z_i] + S @ Wep + bep (packed over k) ----
    for (int t = tid; t < NPG * EMB; t += NT) {
        int i = t >> 5, m = t & 31;
        const ull* s2 = (const ull*)(Ssum + i * KGB);
        ull acc = 0;
        #pragma unroll
        for (int kk = 0; kk < KGB/2; ++kk)
            acc = ffma2(s2[kk], sWep2[kk * EMB + m], acc);
        float lo, hi; upk2(acc, lo, hi);
        Gnf[t] = sAe[sZ[i] * EMB + m] + sBep[m] + lo + hi;
    }
    __syncthreads();

    // ---- Stage E: node_feat = gnf @ W_nodes + b_nodes (2 dims/thread) ----
    {
        const int d0 = tid & 31;
        const int isub = tid >> 5;                     // 0..7
        ull wA[EMB/2], wB[EMB/2];
        #pragma unroll
        for (int mm = 0; mm < EMB/2; ++mm) {
            wA[mm] = pk2(Wn[(2*mm)*DH + d0],      Wn[(2*mm+1)*DH + d0]);
            wB[mm] = pk2(Wn[(2*mm)*DH + d0 + 32], Wn[(2*mm+1)*DH + d0 + 32]);
        }
        const float bA = sBn[d0], bB = sBn[d0 + 32];
        for (int i = isub; i < NPG; i += 8) {
            const ull* g2 = (const ull*)(Gnf + i * EMB);
            ull accA = 0, accB = 0;
            #pragma unroll
            for (int mm = 0; mm < EMB/2; ++mm) {
                ull v = g2[mm];
                accA = ffma2(v, wA[mm], accA);
                accB = ffma2(v, wB[mm], accB);
            }
            float l0, h0, l1, h1; upk2(accA, l0, h0); upk2(accB, l1, h1);
            out_nodes[(size_t)(zbase + i) * DH + d0]      = bA + l0 + h0;
            out_nodes[(size_t)(zbase + i) * DH + d0 + 32] = bB + l1 + h1;
        }
    }

    // ---- Stage F: edge_feat = P[dst_l][src_l] @ W_edges + b_edges ----
    // warp = one edge (broadcast P row); lane d0 computes dims d0 and d0+32
    {
        const int d0 = tid & 31;
        const int esub = tid >> 5;                     // 0..7
        ull wA[KGB/2], wB[KGB/2];
        #pragma unroll
        for (int kk = 0; kk < KGB/2; ++kk) {
            wA[kk] = pk2(We[(2*kk)*DH + d0],      We[(2*kk+1)*DH + d0]);
            wB[kk] = pk2(We[(2*kk)*DH + d0 + 32], We[(2*kk+1)*DH + d0 + 32]);
        }
        const int ebase = g * EPG;
        const float bA = sBe[d0], bB = sBe[d0 + 32];
        #pragma unroll 2
        for (int e = esub; e < EPG; e += 8) {
            const ulonglong2* pv = (const ulonglong2*)(P + sPair[e]);
            ull accA = 0, accB = 0;
            #pragma unroll
            for (int q = 0; q < 8; ++q) {
                ulonglong2 v = pv[q];                  // 4 floats (2 k-pairs)
                accA = ffma2(v.x, wA[2*q+0], accA);
                accB = ffma2(v.x, wB[2*q+0], accB);
                accA = ffma2(v.y, wA[2*q+1], accA);
                accB = ffma2(v.y, wB[2*q+1], accB);
            }
            float l0, h0, l1, h1; upk2(accA, l0, h0); upk2(accB, l1, h1);
            float* o = out_edges + (size_t)(ebase + e) * DH;
            o[d0]      = bA + l0 + h0;
            o[d0 + 32] = bB + l1 + h1;
        }
    }
}

extern "C" void kernel_launch(void* const* d_in, const int* in_sizes, int n_in,
                              void* d_out, int out_size)
{
    const int*   z    = (const int*)  d_in[0];
    const float* pos  = (const float*)d_in[1];
    const int*   ei   = (const int*)  d_in[3];
    const float* ae   = (const float*)d_in[4];
    const float* Wep  = (const float*)d_in[5];
    const float* bep  = (const float*)d_in[6];
    const float* mea  = (const float*)d_in[7];
    const float* stds = (const float*)d_in[8];
    const float* gmul = (const float*)d_in[9];
    const float* gbia = (const float*)d_in[10];
    const float* Wn   = (const float*)d_in[11];
    const float* bn   = (const float*)d_in[12];
    const float* We   = (const float*)d_in[13];
    const float* be   = (const float*)d_in[14];

    const int N = in_sizes[0];          // 49152
    const int E = in_sizes[3] / 2;      // 589824
    const int g = N / NPG;              // 2048

    float* out_nodes = (float*)d_out;
    float* out_edges = out_nodes + (size_t)N * DH;

    cudaFuncSetAttribute(gps_graph_kernel,
                         cudaFuncAttributeMaxDynamicSharedMemorySize, SMEM_BYTES);

    gps_graph_kernel<<<g, NT, SMEM_BYTES>>>(
        z, pos, ei, ae, Wep, bep, mea, stds, gmul, gbia,
        Wn, bn, We, be, out_nodes, out_edges, E);
}